// round 4
// baseline (speedup 1.0000x reference)
#include <cuda_runtime.h>
#include <cstdint>

// SMPL forward kinematics, HBM-bound. Round 4:
// Persistent single-warp blocks (4/SM), double-buffered cp.async pipeline so
// DRAM requests flow continuously across each block's compute/store phases.
//
// Math (G-conjugations cancel):
//   out[b,j] = out[b,P[j]] + R_{b,P[j]} * v_j,  out[b,0] = 0
//   v_j = (off[j][1], off[j][2], off[j][0])
//
// Per tile (32 batches):
//  1) 54 cp.async.cg 16B per thread: coalesced global -> swizzled smem [e][b]
//  2) per-thread FK from smem (swizzle is a lane permutation -> conflict-free)
//  3) results transposed back through smem -> coalesced STG.128

#define NB    32          // batches per tile (== blockDim.x)
#define NF4   54          // float4 per batch, input  (24*9 floats)
#define OF4   18          // float4 per batch, output (24*3 floats)
#define BUF4  (NF4 * NB)  // float4 per buffer
#define SMEM_BYTES (2 * BUF4 * 16)   // 55,296 B -> 4 blocks/SM
#define GRID  608         // 152 SMs * 4 persistent blocks

// swizzled index within one buffer for logical [e][b]
#define SWZ(e, b) ((e) * NB + (((b) ^ (e)) & (NB - 1)))

__device__ __forceinline__ void cp_async16(uint32_t saddr, const void* gptr) {
    asm volatile("cp.async.cg.shared.global [%0], [%1], 16;\n"
                 :: "r"(saddr), "l"(gptr));
}
__device__ __forceinline__ void cp_commit() {
    asm volatile("cp.async.commit_group;\n");
}
template<int N> __device__ __forceinline__ void cp_wait() {
    asm volatile("cp.async.wait_group %0;\n" :: "n"(N));
}

__global__ __launch_bounds__(NB, 4)
void smpl_fk_kernel(const float4* __restrict__ orient,
                    const float*  __restrict__ off,
                    float4*       __restrict__ out,
                    int Btotal)
{
    extern __shared__ float4 sm[];   // [2][NF4][NB], swizzled
    const int tid    = threadIdx.x;
    const int nTiles = (Btotal + NB - 1) / NB;
    int t = blockIdx.x;
    if (t >= nTiles) return;

    uint32_t smemBase;
    asm("{ .reg .u64 u; cvta.to.shared.u64 u, %1; cvt.u32.u64 %0, u; }"
        : "=r"(smemBase) : "l"(sm));

    // ---- prefetch helper (inlined manually below via lambda-like macro) ----
    auto prefetch = [&](int tile, int buf) {
        const int      total = ((Btotal - tile * NB < NB) ? (Btotal - tile * NB) : NB) * NF4;
        const float4*  gbase = orient + (long long)tile * NB * NF4;
        const uint32_t sbase = smemBase + (uint32_t)buf * BUF4 * 16u;
#pragma unroll
        for (int it = 0; it < NF4; ++it) {
            const int g = it * NB + tid;
            if (g < total) {
                const int b = g / NF4;
                const int e = g - b * NF4;
                cp_async16(sbase + (uint32_t)SWZ(e, b) * 16u, gbase + g);
            }
        }
        cp_commit();
    };

    prefetch(t, 0);
    int buf = 0;

    while (true) {
        const int  tn      = t + GRID;
        const bool hasNext = (tn < nTiles);
        if (hasNext) {
            prefetch(tn, buf ^ 1);
            cp_wait<1>();           // current tile's group complete, next still pending
        } else {
            cp_wait<0>();
        }
        __syncthreads();

        const float4* sb = sm + buf * BUF4;
        const int nb = (Btotal - t * NB < NB) ? (Btotal - t * NB) : NB;

        // ---------------- compute: per-thread FK ----------------
        float px[24], py[24], pz[24];
        if (tid < nb) {
            constexpr int PAR[24] = {-1,0,1,2,3,0,5,6,7,0,9,10,11,12,11,14,15,16,17,11,19,20,21,22};
            px[0] = 0.f; py[0] = 0.f; pz[0] = 0.f;
#pragma unroll
            for (int j = 1; j < 24; ++j) {
                const int p  = PAR[j];
                const int w0 = 9 * p;      // first word of matrix p in the record
                const int c0 = w0 >> 2;    // float4 chunk (compile-time)
                const int r  = w0 & 3;     // word offset (compile-time)

                const float4 A = sb[SWZ(c0 + 0, tid)];
                const float4 Bq= sb[SWZ(c0 + 1, tid)];
                const float4 C = sb[SWZ(c0 + 2, tid)];
                float m[12];
                m[0]=A.x;  m[1]=A.y;  m[2]=A.z;  m[3]=A.w;
                m[4]=Bq.x; m[5]=Bq.y; m[6]=Bq.z; m[7]=Bq.w;
                m[8]=C.x;  m[9]=C.y;  m[10]=C.z; m[11]=C.w;

                const float vx = __ldg(off + j * 3 + 1);   // v_j = G * off_j
                const float vy = __ldg(off + j * 3 + 2);
                const float vz = __ldg(off + j * 3 + 0);

                px[j] = fmaf(m[r+0], vx, fmaf(m[r+1], vy, fmaf(m[r+2], vz, px[p])));
                py[j] = fmaf(m[r+3], vx, fmaf(m[r+4], vy, fmaf(m[r+5], vz, py[p])));
                pz[j] = fmaf(m[r+6], vx, fmaf(m[r+7], vy, fmaf(m[r+8], vz, pz[p])));
            }
        }
        // no sync needed: thread tid only reads/writes column tid of this buffer

        // ---------------- stage out: registers -> transposed smem (reuse buffer) ----------------
        float4* so = sm + buf * BUF4;
        if (tid < nb) {
#pragma unroll
            for (int e = 0; e < OF4; ++e) {
                float4 o;
                #define COMPW(w) (((w) % 3 == 0) ? px[(w) / 3] : (((w) % 3 == 1) ? py[(w) / 3] : pz[(w) / 3]))
                o.x = COMPW(4 * e + 0);
                o.y = COMPW(4 * e + 1);
                o.z = COMPW(4 * e + 2);
                o.w = COMPW(4 * e + 3);
                #undef COMPW
                so[SWZ(e, tid)] = o;
            }
        }
        __syncthreads();   // out-stage writes visible before cross-column reads

        // ---------------- write out: transposed smem -> coalesced global ----------------
        {
            float4* obase = out + (long long)t * NB * OF4;
            const int total = nb * OF4;
#pragma unroll
            for (int it = 0; it < OF4; ++it) {
                const int g = it * NB + tid;
                if (g < total) {
                    const int b = g / OF4;
                    const int e = g - b * OF4;
                    obase[g] = so[SWZ(e, b)];
                }
            }
        }
        __syncthreads();   // all reads of this buffer done before it is prefetch target again

        if (!hasNext) break;
        t = tn;
        buf ^= 1;
    }
}

extern "C" void kernel_launch(void* const* d_in, const int* in_sizes, int n_in,
                              void* d_out, int out_size)
{
    const float4* orient = (const float4*)d_in[0];   // (B, 24, 3, 3) fp32
    const float*  off    = (const float* )d_in[1];   // (24, 3) fp32
    float4*       out    = (float4*)d_out;           // (B, 24, 3) fp32

    const int B = in_sizes[0] / 216;
    const int nTiles = (B + NB - 1) / NB;
    const int grid = (nTiles < GRID) ? nTiles : GRID;

    cudaFuncSetAttribute(smpl_fk_kernel,
                         cudaFuncAttributeMaxDynamicSharedMemorySize, SMEM_BYTES);
    smpl_fk_kernel<<<grid, NB, SMEM_BYTES>>>(orient, off, out, B);
}

// round 5
// speedup vs baseline: 1.0338x; 1.0338x over previous
#include <cuda_runtime.h>
#include <cstdint>

// SMPL forward kinematics, HBM-bound. Round 5:
// Round-4's double-buffered cp.async pipeline at Round-3's warp count:
// 16-batch tiles -> 2 x 13,824 B buffers/block -> 8 persistent single-warp
// blocks per SM, each streaming continuously.
//
// Math (G-conjugations cancel):
//   out[b,j] = out[b,P[j]] + R_{b,P[j]} * v_j,  out[b,0] = 0
//   v_j = (off[j][1], off[j][2], off[j][0])   (offsets are fixed constants)

#define NB    16                 // batches per tile
#define TF4   (NB * 54)          // float4 per tile, input  (864)
#define TO4   (NB * 18)          // float4 per tile, output (288)
#define BUFB  (TF4 * 16)         // bytes per buffer (13,824)
#define GRID  1216               // 152 SMs * 8 persistent blocks

// swizzled float4 index within one buffer for logical [e][b], b in [0,16)
#define SWZ(e, b) ((e) * NB + (((b) ^ ((e) & (NB - 1)))))

__device__ __forceinline__ void cp_async16(uint32_t saddr, const void* gptr) {
    asm volatile("cp.async.cg.shared.global [%0], [%1], 16;\n" :: "r"(saddr), "l"(gptr));
}
__device__ __forceinline__ void cp_commit() {
    asm volatile("cp.async.commit_group;\n");
}
template<int N> __device__ __forceinline__ void cp_wait() {
    asm volatile("cp.async.wait_group %0;\n" :: "n"(N));
}

// v_j = G * off_j, hardcoded from the reference's constant SMPL_OFFSETS
__device__ constexpr float VXC[24] = {0.f, 0.0372f, 0.0276f, -0.0094f, 0.0261f, -0.0383f,
    -0.0275f, 0.0121f, -0.0221f, 0.0028f, 0.0028f, -0.0014f, -0.0085f, 0.0064f, 0.0455f,
    0.078f, 0.1621f, 0.1687f, 0.055f, -0.0527f, -0.0719f, -0.1651f, -0.1708f, -0.0563f};
__device__ constexpr float VYC[24] = {0.f, -0.0522f, -0.2453f, -0.271f, -0.0383f, -0.0575f,
    -0.2436f, -0.2666f, -0.0394f, 0.079f, 0.0876f, 0.0356f, 0.1343f, 0.0565f, 0.0724f,
    0.0287f, -0.0099f, 0.0081f, -0.0068f, 0.0714f, 0.0297f, -0.0091f, 0.0043f, -0.0055f};
__device__ constexpr float VZC[24] = {0.f, -0.0112f, 0.0051f, -0.0238f, 0.0775f, -0.0086f,
    -0.0031f, -0.0219f, 0.0827f, -0.0244f, 0.017f, 0.0018f, -0.0212f, 0.032f, -0.012f,
    -0.0121f, -0.0146f, -0.0047f, -0.0099f, -0.015f, -0.0054f, -0.0198f, -0.0038f, -0.0064f};

__global__ __launch_bounds__(32, 8)
void smpl_fk_kernel(const float4* __restrict__ orient,
                    float4*       __restrict__ out,
                    int Btotal)
{
    __shared__ float4 sm[2 * TF4];   // two ping-pong buffers, 27,648 B total
    const int tid    = threadIdx.x;
    const int nTiles = (Btotal + NB - 1) / NB;
    int t = blockIdx.x;
    if (t >= nTiles) return;

    uint32_t smemBase;
    asm("{ .reg .u64 u; cvta.to.shared.u64 u, %1; cvt.u32.u64 %0, u; }"
        : "=r"(smemBase) : "l"(sm));

    auto prefetch = [&](int tile, int bufsel) {
        const float4*  g     = orient + (long long)tile * TF4;
        const int      total = ((Btotal - tile * NB < NB) ? (Btotal - tile * NB) : NB) * 54;
        const uint32_t sb    = smemBase + (uint32_t)bufsel * BUFB;
#pragma unroll
        for (int it = 0; it < TF4 / 32; ++it) {      // 27 iterations
            const int idx = it * 32 + tid;
            if (idx < total) {
                const int b = idx / 54;
                const int e = idx - b * 54;
                cp_async16(sb + (uint32_t)SWZ(e, b) * 16u, g + idx);
            }
        }
        cp_commit();
    };

    prefetch(t, 0);
    int buf = 0;

    while (true) {
        const int  tn      = t + GRID;
        const bool hasNext = (tn < nTiles);
        if (hasNext) {
            prefetch(tn, buf ^ 1);
            cp_wait<1>();            // current tile's copy complete; next still in flight
        } else {
            cp_wait<0>();
        }
        __syncthreads();

        const float4* sb = sm + buf * TF4;
        const int nb = (Btotal - t * NB < NB) ? (Btotal - t * NB) : NB;

        // ---------------- compute: lanes 0..15, one batch each ----------------
        float px[24], py[24], pz[24];
        if (tid < nb) {
            constexpr int PAR[24] = {-1,0,1,2,3,0,5,6,7,0,9,10,11,12,11,14,15,16,17,11,19,20,21,22};
            px[0] = 0.f; py[0] = 0.f; pz[0] = 0.f;
#pragma unroll
            for (int j = 1; j < 24; ++j) {
                const int p  = PAR[j];
                const int w0 = 9 * p;      // first word of matrix p in the record
                const int c0 = w0 >> 2;    // float4 chunk (compile-time)
                const int r  = w0 & 3;     // word offset (compile-time)

                const float4 A = sb[SWZ(c0 + 0, tid)];
                const float4 Bq= sb[SWZ(c0 + 1, tid)];
                const float4 C = sb[SWZ(c0 + 2, tid)];
                float m[12];
                m[0]=A.x;  m[1]=A.y;  m[2]=A.z;  m[3]=A.w;
                m[4]=Bq.x; m[5]=Bq.y; m[6]=Bq.z; m[7]=Bq.w;
                m[8]=C.x;  m[9]=C.y;  m[10]=C.z; m[11]=C.w;

                px[j] = fmaf(m[r+0], VXC[j], fmaf(m[r+1], VYC[j], fmaf(m[r+2], VZC[j], px[p])));
                py[j] = fmaf(m[r+3], VXC[j], fmaf(m[r+4], VYC[j], fmaf(m[r+5], VZC[j], py[p])));
                pz[j] = fmaf(m[r+6], VXC[j], fmaf(m[r+7], VYC[j], fmaf(m[r+8], VZC[j], pz[p])));
            }
        }
        // thread t only touches column t between here and the barrier: no sync needed

        // ---------------- stage out: registers -> transposed smem (reuse buffer) ----------------
        float4* so = sm + buf * TF4;
        if (tid < nb) {
#pragma unroll
            for (int e = 0; e < 18; ++e) {
                float4 o;
                #define COMPW(w) (((w) % 3 == 0) ? px[(w) / 3] : (((w) % 3 == 1) ? py[(w) / 3] : pz[(w) / 3]))
                o.x = COMPW(4 * e + 0);
                o.y = COMPW(4 * e + 1);
                o.z = COMPW(4 * e + 2);
                o.w = COMPW(4 * e + 3);
                #undef COMPW
                so[SWZ(e, tid)] = o;
            }
        }
        __syncthreads();   // stage-out visible to all lanes before cross-column reads

        // ---------------- write out: transposed smem -> coalesced global ----------------
        {
            float4* obase = out + (long long)t * TO4;
            const int total = nb * 18;
#pragma unroll
            for (int it = 0; it < TO4 / 32; ++it) {  // 9 iterations
                const int g = it * 32 + tid;
                if (g < total) {
                    const int b = g / 18;
                    const int e = g - b * 18;
                    obase[g] = so[SWZ(e, b)];
                }
            }
        }
        __syncthreads();   // buffer fully consumed before it becomes a prefetch target

        if (!hasNext) break;
        t = tn;
        buf ^= 1;
    }
}

extern "C" void kernel_launch(void* const* d_in, const int* in_sizes, int n_in,
                              void* d_out, int out_size)
{
    const float4* orient = (const float4*)d_in[0];   // (B, 24, 3, 3) fp32
    float4*       out    = (float4*)d_out;           // (B, 24, 3) fp32

    const int B = in_sizes[0] / 216;
    const int nTiles = (B + NB - 1) / NB;
    const int grid = (nTiles < GRID) ? nTiles : GRID;

    cudaFuncSetAttribute(smpl_fk_kernel,
                         cudaFuncAttributePreferredSharedMemoryCarveout, 100);
    smpl_fk_kernel<<<grid, 32>>>(orient, out, B);
}